// round 10
// baseline (speedup 1.0000x reference)
#include <cuda_runtime.h>
#include <cstdint>
#include <cstddef>

// ---------------------------------------------------------------------------
// NeuralODE Dopri5 — ONE persistent kernel for the whole integration.
// 720 GEMM phases (40 steps x 6 evals x 3 layers) separated by a software
// global barrier (grid=128 CTAs, 1/SM, all co-resident). Per-phase GEMM is
// the R9 design: mma.sync m16n8k8 TF32, 3xTF32 split, BK=64, triple-buffered
// smem, 2-stage lookahead, ldmatrix fragments. Cross-CTA traffic via L2
// (__ldcg) + __threadfence + barrier. RK combine fused into L3 epilogue.
// ---------------------------------------------------------------------------

#define BB 1024
#define DD 256
#define HH 512
#define N_STEPS 40
#define GRID 128
#define RKC(x) ((float)(0.25 * (x)))

__device__ float g_y   [BB * DD];
__device__ float g_ycmb[BB * DD];
__device__ float g_k [6][BB * DD];
__device__ float g_h1[BB * HH];
__device__ float g_h2[BB * HH];
__device__ float g_W1hi[HH * DD], g_W1lo[HH * DD];
__device__ float g_W2hi[HH * HH], g_W2lo[HH * HH];
__device__ float g_W3hi[DD * HH], g_W3lo[DD * HH];
__device__ unsigned int g_bar;

// Dopri5 tableau * h (h = 0.25), rounded exactly as the host code did.
__device__ const float c_A[5][5] = {
    { RKC(1.0/5.0), 0, 0, 0, 0 },
    { RKC(3.0/40.0), RKC(9.0/40.0), 0, 0, 0 },
    { RKC(44.0/45.0), RKC(-56.0/15.0), RKC(32.0/9.0), 0, 0 },
    { RKC(19372.0/6561.0), RKC(-25360.0/2187.0), RKC(64448.0/6561.0),
      RKC(-212.0/729.0), 0 },
    { RKC(9017.0/3168.0), RKC(-355.0/33.0), RKC(46732.0/5247.0),
      RKC(49.0/176.0), RKC(-5103.0/18656.0) } };
__device__ const float c_Bf[5] = {
    RKC(35.0/384.0), RKC(500.0/1113.0), RKC(125.0/192.0),
    RKC(-2187.0/6784.0), RKC(11.0/84.0) };

// ----------------------------- helpers -------------------------------------
__device__ __forceinline__ uint32_t smem_u32(const void* p) {
    uint32_t a;
    asm("{ .reg .u64 t; cvta.to.shared.u64 t, %1; cvt.u32.u64 %0, t; }"
        : "=r"(a) : "l"(p));
    return a;
}
__device__ __forceinline__ void tf32split(float x, uint32_t& hi, uint32_t& lo) {
    uint32_t h; asm("cvt.rna.tf32.f32 %0, %1;" : "=r"(h) : "f"(x));
    float r = x - __uint_as_float(h);
    asm("cvt.rna.tf32.f32 %0, %1;" : "=r"(lo) : "f"(r));
    hi = h;
}
__device__ __forceinline__ void sts128(uint32_t a, uint32_t x, uint32_t y,
                                       uint32_t z, uint32_t w) {
    asm volatile("st.shared.v4.b32 [%0], {%1,%2,%3,%4};"
                 :: "r"(a), "r"(x), "r"(y), "r"(z), "r"(w) : "memory");
}
__device__ __forceinline__ void cp16(uint32_t d, const float* s) {
    asm volatile("cp.async.cg.shared.global [%0], [%1], 16;"
                 :: "r"(d), "l"(s) : "memory");
}
__device__ __forceinline__ void cp_commit() {
    asm volatile("cp.async.commit_group;" ::: "memory");
}
__device__ __forceinline__ void cp_wait1() {
    asm volatile("cp.async.wait_group 1;" ::: "memory");
}
__device__ __forceinline__ void cp_wait0() {
    asm volatile("cp.async.wait_group 0;" ::: "memory");
}
__device__ __forceinline__ void ldm4(uint32_t* r, uint32_t addr) {
    asm volatile("ldmatrix.sync.aligned.m8n8.x4.shared.b16 {%0,%1,%2,%3}, [%4];"
                 : "=r"(r[0]), "=r"(r[1]), "=r"(r[2]), "=r"(r[3]) : "r"(addr));
}
__device__ __forceinline__ void mma8(float* d, const uint32_t* a,
                                     uint32_t b0, uint32_t b1) {
    asm volatile(
        "mma.sync.aligned.m16n8k8.row.col.f32.tf32.tf32.f32 "
        "{%0,%1,%2,%3}, {%4,%5,%6,%7}, {%8,%9}, {%0,%1,%2,%3};"
        : "+f"(d[0]), "+f"(d[1]), "+f"(d[2]), "+f"(d[3])
        : "r"(a[0]), "r"(a[1]), "r"(a[2]), "r"(a[3]), "r"(b0), "r"(b1));
}

// Global barrier: all GRID CTAs arrive; pass when count reaches target.
__device__ __forceinline__ void gbarrier(unsigned int target) {
    __threadfence();                 // publish this CTA's stores to L2
    __syncthreads();                 // all threads' fences done
    if (threadIdx.x == 0) {
        atomicAdd(&g_bar, 1u);
        unsigned int v;
        for (;;) {
            asm volatile("ld.acquire.gpu.u32 %0, [%1];" : "=r"(v) : "l"(&g_bar));
            if (v >= target) break;
            __nanosleep(64);
        }
    }
    __syncthreads();                 // release the CTA past the flag
}

// ---------------------------------------------------------------------------
// One GEMM phase: C[tile] = act(A @ W^T + bias). 256 threads, warp grid
// 2(M) x 4(N), warp tile (16*MT) x 16, CTA tile (32*MT) x 64. BK=64,
// 3 smem buffers, 2-stage lookahead, XOR-swizzled 128B rows.
// Mutable gmem reads use __ldcg (L2) — L1 is not flushed inside the kernel.
// MODE 0: relu fp32 store. MODE 1: store + fused RK combine (ksel/kc/nks,
// cself, aux, optional emit at time t).
// ---------------------------------------------------------------------------
template<int MT, int MODE>
__device__ __forceinline__ void gemm_phase(
    const float* __restrict__ A,
    const float* __restrict__ Whi, const float* __restrict__ Wlo,
    const float* __restrict__ bias, float* __restrict__ C,
    const int K, const int N, const int m0, const int n0, const uint32_t sb,
    const float* __restrict__ yin, const int* ksel, const float* kc,
    const int nks, const float cself, float* __restrict__ aux,
    float* __restrict__ emit, const int t)
{
    constexpr int BM = 32 * MT;
    constexpr uint32_t AB = (uint32_t)BM * 256;
    constexpr uint32_t WB = 64 * 256;
    constexpr uint32_t ASUB = (uint32_t)BM * 128;
    constexpr uint32_t WSUB = 64 * 128;
    constexpr uint32_t WOFFS = 2 * AB;
    constexpr uint32_t STRIDE = 2 * AB + 2 * WB;

    const int tid  = threadIdx.x;
    const int warp = tid >> 5, lane = tid & 31;
    const int wM = warp >> 2, wN = warp & 3;
    const int g = lane >> 2, c = lane & 3;

    const int lr  = tid >> 3;
    const int lc4 = (tid & 7) * 4;
    const uint32_t ssc = ((uint32_t)lc4 ^ (((uint32_t)lr & 7) << 2)) * 4;

    const int quad = lane >> 3, l8 = lane & 7;
    const int arow = ((quad & 1) << 3) + l8;
    const uint32_t kcA = (uint32_t)((quad & 2) << 1);
    const int brow = ((quad & 2) << 2) + l8;
    const uint32_t kcB = (uint32_t)((quad & 1) << 2);

    uint32_t aoff[MT];
    #pragma unroll
    for (int i = 0; i < MT; i++)
        aoff[i] = (uint32_t)(wM * 16 * MT + i * 16 + arow) * 128;
    const uint32_t swzA = ((uint32_t)(arow & 7)) << 2;
    const uint32_t boff = (uint32_t)(wN * 16 + brow) * 128;
    const uint32_t swzB = ((uint32_t)(brow & 7)) << 2;

    const int S = K >> 6;
    float4 pa[2][MT];

    auto ldA = [&](int s) {
        #pragma unroll
        for (int tt = 0; tt < 2; tt++)
            #pragma unroll
            for (int q = 0; q < MT; q++) {
                const int row = lr + q * 32;
                pa[tt][q] = __ldcg((const float4*)(A + (size_t)(m0 + row) * K
                                                   + (s << 6) + tt * 32 + lc4));
            }
    };
    auto stA = [&](int buf) {
        const uint32_t b0 = sb + (uint32_t)buf * STRIDE;
        #pragma unroll
        for (int tt = 0; tt < 2; tt++)
            #pragma unroll
            for (int q = 0; q < MT; q++) {
                const int row = lr + q * 32;
                const uint32_t d = b0 + (uint32_t)tt * ASUB
                                 + (uint32_t)row * 128 + ssc;
                uint32_t hx, hy, hz, hw, lx, ly, lz, lw;
                tf32split(pa[tt][q].x, hx, lx); tf32split(pa[tt][q].y, hy, ly);
                tf32split(pa[tt][q].z, hz, lz); tf32split(pa[tt][q].w, hw, lw);
                sts128(d,      hx, hy, hz, hw);
                sts128(d + AB, lx, ly, lz, lw);
            }
    };
    auto cpW = [&](int s, int buf) {
        const uint32_t w0 = sb + (uint32_t)buf * STRIDE + WOFFS;
        #pragma unroll
        for (int tt = 0; tt < 2; tt++)
            #pragma unroll
            for (int q = 0; q < 2; q++) {
                const int row = lr + q * 32;
                const size_t off = (size_t)(n0 + row) * K + (s << 6) + tt * 32 + lc4;
                const uint32_t d = w0 + (uint32_t)tt * WSUB
                                 + (uint32_t)row * 128 + ssc;
                cp16(d,      Whi + off);
                cp16(d + WB, Wlo + off);
            }
    };

    float acc[MT][2][4];
    #pragma unroll
    for (int i = 0; i < MT; i++)
        #pragma unroll
        for (int nt = 0; nt < 2; nt++)
            #pragma unroll
            for (int q = 0; q < 4; q++) acc[i][nt][q] = 0.0f;

    ldA(0);
    stA(0);
    ldA(1);
    cpW(0, 0); cp_commit();
    cpW(1, 1); cp_commit();

    int cur = 0, nxt = 1, nx2 = 2;

    for (int s = 0; s < S; s++) {
        cp_wait1();
        __syncthreads();

        if (s + 1 < S) stA(nxt);
        if (s + 2 < S) { ldA(s + 2); cpW(s + 2, nx2); }
        cp_commit();

        const uint32_t base = sb + (uint32_t)cur * STRIDE;
        uint32_t ah[2][MT][4], al[2][MT][4], bh[2][4], bl[2][4];

        auto ldfrag = [&](int j, int fb) {
            const int tt = j >> 2, jj = j & 3;
            const uint32_t colA = (((8u * jj) | kcA) ^ swzA) * 4;
            const uint32_t colB = (((8u * jj) | kcB) ^ swzB) * 4;
            const uint32_t ab = base + (uint32_t)tt * ASUB;
            const uint32_t wb = base + WOFFS + (uint32_t)tt * WSUB;
            #pragma unroll
            for (int i = 0; i < MT; i++) {
                ldm4(ah[fb][i], ab + aoff[i] + colA);
                ldm4(al[fb][i], ab + AB + aoff[i] + colA);
            }
            ldm4(bh[fb], wb + boff + colB);
            ldm4(bl[fb], wb + WB + boff + colB);
        };

        ldfrag(0, 0);
        #pragma unroll
        for (int j = 0; j < 8; j++) {
            const int fb = j & 1;
            if (j < 7) ldfrag(j + 1, fb ^ 1);
            #pragma unroll
            for (int i = 0; i < MT; i++) {
                mma8(acc[i][0], ah[fb][i], bh[fb][0], bh[fb][1]);
                mma8(acc[i][1], ah[fb][i], bh[fb][2], bh[fb][3]);
                mma8(acc[i][0], ah[fb][i], bl[fb][0], bl[fb][1]);
                mma8(acc[i][1], ah[fb][i], bl[fb][2], bl[fb][3]);
                mma8(acc[i][0], al[fb][i], bh[fb][0], bh[fb][1]);
                mma8(acc[i][1], al[fb][i], bh[fb][2], bh[fb][3]);
            }
        }

        const int tmp = cur; cur = nxt; nxt = nx2; nx2 = tmp;
    }
    cp_wait0();   // drain: next phase reuses these smem buffers

    // ---- epilogue ----
    #pragma unroll
    for (int i = 0; i < MT; i++) {
        #pragma unroll
        for (int nt = 0; nt < 2; nt++) {
            const int col  = n0 + wN * 16 + nt * 8 + 2 * c;
            const float b0v = __ldg(bias + col), b1v = __ldg(bias + col + 1);
            const int row0 = m0 + wM * 16 * MT + i * 16 + g;
            #pragma unroll
            for (int hh = 0; hh < 2; hh++) {
                const int row = row0 + 8 * hh;
                float v0 = acc[i][nt][2 * hh + 0] + b0v;
                float v1 = acc[i][nt][2 * hh + 1] + b1v;
                const size_t idx = (size_t)row * N + col;
                if (MODE == 0) {
                    v0 = fmaxf(v0, 0.0f); v1 = fmaxf(v1, 0.0f);
                    *(float2*)(C + idx) = make_float2(v0, v1);
                } else {
                    *(float2*)(C + idx) = make_float2(v0, v1);
                    float2 yv = __ldcg((const float2*)(yin + idx));
                    float a0 = yv.x + cself * v0;
                    float a1 = yv.y + cself * v1;
                    for (int j = 0; j < nks; j++) {
                        const float* kp = &g_k[0][0] + (size_t)ksel[j] * (BB * DD) + idx;
                        float2 kv = __ldcg((const float2*)kp);
                        a0 += kc[j] * kv.x;
                        a1 += kc[j] * kv.y;
                    }
                    *(float2*)(aux + idx) = make_float2(a0, a1);
                    if (emit) {
                        const size_t o = (size_t)row * (10 * DD) + (size_t)t * DD + col;
                        *(float2*)(emit + o) = make_float2(a0, a1);
                    }
                }
            }
        }
    }
}

// ---------------------------------------------------------------------------
// Persistent kernel: all 720 phases.
// ---------------------------------------------------------------------------
__global__ __launch_bounds__(256, 1)
void ode_kernel(const float* __restrict__ b1, const float* __restrict__ b2,
                const float* __restrict__ b3, float* __restrict__ out)
{
    extern __shared__ float smem[];
    const uint32_t sb = smem_u32(smem);
    const int bid = blockIdx.x;

    // tile maps (grid = 128)
    const int m12 = (bid >> 3) * 64, n12 = (bid & 7) * 64;   // L1/L2: 16x8
    const int m3  = (bid >> 2) * 32, n3  = (bid & 3) * 64;   // L3:   32x4

    unsigned int target = 0;

    #pragma unroll 1
    for (int step = 0; step < N_STEPS; step++) {
        #pragma unroll 1
        for (int s = 0; s < 6; s++) {
            const float* Ain = (s == 0) ? g_y : g_ycmb;

            gemm_phase<2, 0>(Ain, g_W1hi, g_W1lo, b1, g_h1, DD, HH,
                             m12, n12, sb, nullptr, nullptr, nullptr,
                             0, 0.0f, nullptr, nullptr, 0);
            target += GRID; gbarrier(target);

            gemm_phase<2, 0>(g_h1, g_W2hi, g_W2lo, b2, g_h2, HH, HH,
                             m12, n12, sb, nullptr, nullptr, nullptr,
                             0, 0.0f, nullptr, nullptr, 0);
            target += GRID; gbarrier(target);

            int   ksel[4];
            float kc[4];
            int   nks;
            float cself;
            float* aux;
            float* emit = nullptr;
            if (s < 5) {
                nks = s;
                for (int j = 0; j < s; j++) { ksel[j] = j; kc[j] = c_A[s][j]; }
                cself = c_A[s][s];
                aux   = g_ycmb;
            } else {
                nks = 4;
                ksel[0] = 0; ksel[1] = 2; ksel[2] = 3; ksel[3] = 4;
                kc[0] = c_Bf[0]; kc[1] = c_Bf[1]; kc[2] = c_Bf[2]; kc[3] = c_Bf[3];
                cself = c_Bf[4];
                aux   = g_y;
                if ((step & 3) == 3) emit = out;
            }
            gemm_phase<1, 1>(g_h2, g_W3hi, g_W3lo, b3, g_k[s], HH, DD,
                             m3, n3, sb, g_y, ksel, kc, nks, cself, aux,
                             emit, step >> 2);
            target += GRID; gbarrier(target);
        }
    }
}

// Split X into tf32 hi/lo parts
__global__ void wsplit_kernel(const float* __restrict__ X,
                              float* __restrict__ hi, float* __restrict__ lo, int n)
{
    int i = blockIdx.x * blockDim.x + threadIdx.x;
    if (i < n) {
        uint32_t h, l;
        tf32split(X[i], h, l);
        hi[i] = __uint_as_float(h);
        lo[i] = __uint_as_float(l);
    }
}

__global__ void zero_bar_kernel() { g_bar = 0u; }

extern "C" void kernel_launch(void* const* d_in, const int* in_sizes, int n_in,
                              void* d_out, int out_size)
{
    (void)in_sizes; (void)n_in; (void)out_size;
    const float* x0 = (const float*)d_in[0];
    // d_in[1] is T (int32, always 11) — baked into the graph.
    const float* W1 = (const float*)d_in[2];
    const float* b1 = (const float*)d_in[3];
    const float* W2 = (const float*)d_in[4];
    const float* b2 = (const float*)d_in[5];
    const float* W3 = (const float*)d_in[6];
    const float* b3 = (const float*)d_in[7];
    float* out = (float*)d_out;

    float *y, *w1h, *w1l, *w2h, *w2l, *w3h, *w3l;
    cudaGetSymbolAddress((void**)&y,   g_y);
    cudaGetSymbolAddress((void**)&w1h, g_W1hi);
    cudaGetSymbolAddress((void**)&w1l, g_W1lo);
    cudaGetSymbolAddress((void**)&w2h, g_W2hi);
    cudaGetSymbolAddress((void**)&w2l, g_W2lo);
    cudaGetSymbolAddress((void**)&w3h, g_W3hi);
    cudaGetSymbolAddress((void**)&w3l, g_W3lo);

    // smem: 3 buffers of (2*AB + 2*WB), MT=2 -> 3 * 65536 = 196608
    const int SMEM = 3 * (2 * 64 * 256 + 2 * 64 * 256);
    cudaFuncSetAttribute((const void*)&ode_kernel,
                         cudaFuncAttributeMaxDynamicSharedMemorySize, SMEM);

    // y = x0[:,0,:]
    cudaMemcpyAsync(y, x0, sizeof(float) * BB * DD, cudaMemcpyDeviceToDevice);

    wsplit_kernel<<<(HH * DD + 255) / 256, 256>>>(W1, w1h, w1l, HH * DD);
    wsplit_kernel<<<(HH * HH + 255) / 256, 256>>>(W2, w2h, w2l, HH * HH);
    wsplit_kernel<<<(DD * HH + 255) / 256, 256>>>(W3, w3h, w3l, DD * HH);
    zero_bar_kernel<<<1, 1>>>();

    ode_kernel<<<GRID, 256, SMEM>>>(b1, b2, b3, out);
}

// round 12
// speedup vs baseline: 1.3685x; 1.3685x over previous
#include <cuda_runtime.h>
#include <cuda_fp16.h>
#include <cstdint>
#include <cstddef>

// ---------------------------------------------------------------------------
// NeuralODE Dopri5. GEMMs: mma.sync m16n8k16 FP16 (2xFP16 split: A=Ah+Al,
// W=Wh+Wl in fp16; compute Ah·Wh + Ah·Wl + Al·Wh, fp32 accum -> ~22-bit
// precision, dropped term ~2^-22). Halves tensor instructions vs 3xTF32.
// A: LDG fp32 -> split -> STS. W: pre-split fp16 hi/lo, cp.async.
// BK=64, triple-buffered smem, 2-stage lookahead, ldmatrix fragments.
// RK combine fused into layer-3 epilogue. 18 launches per RK step.
// ---------------------------------------------------------------------------

#define BB 1024
#define DD 256
#define HH 512
#define N_STEPS 40
#define HSTEP 0.25f

__device__ float g_y   [BB * DD];
__device__ float g_ycmb[BB * DD];
__device__ float g_k [6][BB * DD];
__device__ float g_h1[BB * HH];
__device__ float g_h2[BB * HH];
__device__ __half g_W1hi[HH * DD], g_W1lo[HH * DD];
__device__ __half g_W2hi[HH * HH], g_W2lo[HH * HH];
__device__ __half g_W3hi[DD * HH], g_W3lo[DD * HH];

struct Epi {
    const float* yin;
    const float* ks[4];
    float        cks[4];
    int          nks;
    float        cself;
    float*       aux;
    float*       emit;
    int          t;
};

// ----------------------------- helpers -------------------------------------
__device__ __forceinline__ uint32_t smem_u32(const void* p) {
    uint32_t a;
    asm("{ .reg .u64 t; cvta.to.shared.u64 t, %1; cvt.u32.u64 %0, t; }"
        : "=r"(a) : "l"(p));
    return a;
}
__device__ __forceinline__ uint32_t packh2(__half a, __half b) {
    __half2 t = __halves2half2(a, b);       // a -> low 16 bits (element k)
    return *reinterpret_cast<uint32_t*>(&t);
}
__device__ __forceinline__ void sts128(uint32_t a, uint32_t x, uint32_t y,
                                       uint32_t z, uint32_t w) {
    asm volatile("st.shared.v4.b32 [%0], {%1,%2,%3,%4};"
                 :: "r"(a), "r"(x), "r"(y), "r"(z), "r"(w) : "memory");
}
__device__ __forceinline__ void cp16(uint32_t d, const void* s) {
    asm volatile("cp.async.cg.shared.global [%0], [%1], 16;"
                 :: "r"(d), "l"(s) : "memory");
}
__device__ __forceinline__ void cp_commit() {
    asm volatile("cp.async.commit_group;" ::: "memory");
}
__device__ __forceinline__ void cp_wait1() {
    asm volatile("cp.async.wait_group 1;" ::: "memory");
}
__device__ __forceinline__ void ldm4(uint32_t* r, uint32_t addr) {
    asm volatile("ldmatrix.sync.aligned.m8n8.x4.shared.b16 {%0,%1,%2,%3}, [%4];"
                 : "=r"(r[0]), "=r"(r[1]), "=r"(r[2]), "=r"(r[3]) : "r"(addr));
}
// m16n8k16 fp16 MMA, fp32 accumulate
__device__ __forceinline__ void mma16(float* d, const uint32_t* a,
                                      uint32_t b0, uint32_t b1) {
    asm volatile(
        "mma.sync.aligned.m16n8k16.row.col.f32.f16.f16.f32 "
        "{%0,%1,%2,%3}, {%4,%5,%6,%7}, {%8,%9}, {%0,%1,%2,%3};"
        : "+f"(d[0]), "+f"(d[1]), "+f"(d[2]), "+f"(d[3])
        : "r"(a[0]), "r"(a[1]), "r"(a[2]), "r"(a[3]), "r"(b0), "r"(b1));
}

// ---------------------------------------------------------------------------
// GEMM: C[M,N] = act(A @ W^T + bias). 256 threads, warp grid 2(M) x 4(N),
// warp tile (16*MT) x 16, CTA tile (32*MT) x 64. BK=64 (4 k16-slices/stage),
// 3 smem buffers, 2-stage lookahead, one barrier per stage.
// Smem rows = 128B (64 fp16), XOR swizzle: 16B-chunk ^= (row&7).
// Stage: Ahi[AB] Alo[AB] Whi[8192] Wlo[8192], AB = BM*128.
// MODE 0: relu fp32 store. MODE 1: linear store + fused RK-combine epilogue.
// ---------------------------------------------------------------------------
template<int MT, int MODE>
__global__ __launch_bounds__(256, 1)
void gemm_tc(const float* __restrict__ A,
             const __half* __restrict__ Whi, const __half* __restrict__ Wlo,
             const float* __restrict__ bias, float* __restrict__ C,
             int K, int N, Epi ep)
{
    constexpr int BM = 32 * MT;
    constexpr int TPR = 256 / BM;                    // threads per A row
    constexpr int AQ  = MT;                          // A 16B chunks / thread
    constexpr uint32_t AB = (uint32_t)BM * 128;      // bytes per A part
    constexpr uint32_t WB = 64 * 128;                // 8192 bytes per W part
    constexpr uint32_t WOFFS = 2 * AB;
    constexpr uint32_t STRIDE = 2 * AB + 2 * WB;

    extern __shared__ float smem[];
    const uint32_t sb = smem_u32(smem);
    const int tid  = threadIdx.x;
    const int warp = tid >> 5, lane = tid & 31;
    const int wM = warp >> 2, wN = warp & 3;
    const int g = lane >> 2, c = lane & 3;
    const int m0 = blockIdx.y * BM, n0 = blockIdx.x * 64;

    // A loader geometry: chunk = 8 k-values (fp32 src 32B -> fp16 16B)
    const int arw  = tid / TPR;                      // 0..BM-1
    const int akc0 = (tid % TPR) * AQ;               // first chunk (of 8)
    // W loader geometry
    const int wrw  = tid >> 2;                       // 0..63
    const int wkc0 = (tid & 3) * 2;

    // ldmatrix geometry
    const int quad = lane >> 3, l8 = lane & 7;
    const uint32_t aqs = (uint32_t)(quad >> 1);      // A k-chunk select
    const uint32_t bqs = (uint32_t)(quad & 1);       // B k-chunk select
    uint32_t aoffA[MT];
    #pragma unroll
    for (int i = 0; i < MT; i++)
        aoffA[i] = (uint32_t)(wM * 16 * MT + i * 16 + ((quad & 1) << 3) + l8) * 128;
    const uint32_t boffB = WOFFS
        + (uint32_t)(wN * 16 + ((quad >> 1) << 3) + l8) * 128;

    const int S = K >> 6;
    float4 pa[AQ][2];

    auto ldA = [&](int s) {
        #pragma unroll
        for (int q = 0; q < AQ; q++) {
            const float* p = A + (size_t)(m0 + arw) * K + (s << 6)
                           + (akc0 + q) * 8;
            pa[q][0] = *(const float4*)p;
            pa[q][1] = *(const float4*)(p + 4);
        }
    };
    auto stA = [&](int buf) {
        #pragma unroll
        for (int q = 0; q < AQ; q++) {
            const int kc = akc0 + q;
            const uint32_t d = sb + (uint32_t)buf * STRIDE
                             + (uint32_t)arw * 128
                             + (uint32_t)((kc ^ (arw & 7)) << 4);
            const float* f = (const float*)&pa[q][0];
            uint32_t hi[4], lo[4];
            #pragma unroll
            for (int e = 0; e < 4; e++) {
                float f0 = f[2 * e], f1 = f[2 * e + 1];
                __half h0 = __float2half_rn(f0), h1 = __float2half_rn(f1);
                hi[e] = packh2(h0, h1);
                __half r0 = __float2half_rn(f0 - __half2float(h0));
                __half r1 = __float2half_rn(f1 - __half2float(h1));
                lo[e] = packh2(r0, r1);
            }
            sts128(d,      hi[0], hi[1], hi[2], hi[3]);
            sts128(d + AB, lo[0], lo[1], lo[2], lo[3]);
        }
    };
    auto cpW = [&](int s, int buf) {
        #pragma unroll
        for (int q = 0; q < 2; q++) {
            const int kc = wkc0 + q;
            const size_t off = (size_t)(n0 + wrw) * K + (s << 6) + kc * 8;
            const uint32_t d = sb + (uint32_t)buf * STRIDE + WOFFS
                             + (uint32_t)wrw * 128
                             + (uint32_t)((kc ^ (wrw & 7)) << 4);
            cp16(d,      Whi + off);
            cp16(d + WB, Wlo + off);
        }
    };

    float acc[MT][2][4];
    #pragma unroll
    for (int i = 0; i < MT; i++)
        #pragma unroll
        for (int nt = 0; nt < 2; nt++)
            #pragma unroll
            for (int q = 0; q < 4; q++) acc[i][nt][q] = 0.0f;

    // prologue
    ldA(0);
    stA(0);
    ldA(1);
    cpW(0, 0); cp_commit();
    cpW(1, 1); cp_commit();

    int cur = 0, nxt = 1, nx2 = 2;

    for (int s = 0; s < S; s++) {
        cp_wait1();
        __syncthreads();

        if (s + 1 < S) stA(nxt);
        if (s + 2 < S) { ldA(s + 2); cpW(s + 2, nx2); }
        cp_commit();

        const uint32_t base = sb + (uint32_t)cur * STRIDE;
        uint32_t ah[2][MT][4], al[2][MT][4], bh[2][4], bl[2][4];

        auto ldfrag = [&](int j, int fb) {
            const uint32_t colA = (uint32_t)(((2 * j + aqs) ^ l8) << 4);
            const uint32_t colB = (uint32_t)(((2 * j + bqs) ^ l8) << 4);
            #pragma unroll
            for (int i = 0; i < MT; i++) {
                ldm4(ah[fb][i], base + aoffA[i] + colA);
                ldm4(al[fb][i], base + AB + aoffA[i] + colA);
            }
            ldm4(bh[fb], base + boffB + colB);
            ldm4(bl[fb], base + WB + boffB + colB);
        };

        ldfrag(0, 0);
        #pragma unroll
        for (int j = 0; j < 4; j++) {           // 4 k16-slices per stage
            const int fb = j & 1;
            if (j < 3) ldfrag(j + 1, fb ^ 1);
            #pragma unroll
            for (int i = 0; i < MT; i++) {
                mma16(acc[i][0], ah[fb][i], bh[fb][0], bh[fb][1]);
                mma16(acc[i][1], ah[fb][i], bh[fb][2], bh[fb][3]);
                mma16(acc[i][0], ah[fb][i], bl[fb][0], bl[fb][1]);
                mma16(acc[i][1], ah[fb][i], bl[fb][2], bl[fb][3]);
                mma16(acc[i][0], al[fb][i], bh[fb][0], bh[fb][1]);
                mma16(acc[i][1], al[fb][i], bh[fb][2], bh[fb][3]);
            }
        }

        const int tmp = cur; cur = nxt; nxt = nx2; nx2 = tmp;
    }

    // ---- epilogue ----
    #pragma unroll
    for (int i = 0; i < MT; i++) {
        #pragma unroll
        for (int nt = 0; nt < 2; nt++) {
            const int col  = n0 + wN * 16 + nt * 8 + 2 * c;
            const float b0v = bias[col], b1v = bias[col + 1];
            const int row0 = m0 + wM * 16 * MT + i * 16 + g;
            #pragma unroll
            for (int hh = 0; hh < 2; hh++) {
                const int row = row0 + 8 * hh;
                float v0 = acc[i][nt][2 * hh + 0] + b0v;
                float v1 = acc[i][nt][2 * hh + 1] + b1v;
                const size_t idx = (size_t)row * N + col;
                if (MODE == 0) {
                    v0 = fmaxf(v0, 0.0f); v1 = fmaxf(v1, 0.0f);
                    *(float2*)(C + idx) = make_float2(v0, v1);
                } else {
                    *(float2*)(C + idx) = make_float2(v0, v1);
                    float a0 = ep.yin[idx]     + ep.cself * v0;
                    float a1 = ep.yin[idx + 1] + ep.cself * v1;
                    for (int t = 0; t < ep.nks; t++) {
                        a0 += ep.cks[t] * ep.ks[t][idx];
                        a1 += ep.cks[t] * ep.ks[t][idx + 1];
                    }
                    *(float2*)(ep.aux + idx) = make_float2(a0, a1);
                    if (ep.emit) {
                        const size_t o = (size_t)row * (10 * DD) + (size_t)ep.t * DD + col;
                        *(float2*)(ep.emit + o) = make_float2(a0, a1);
                    }
                }
            }
        }
    }
}

// Split W into fp16 hi/lo parts
__global__ void wsplit_kernel(const float* __restrict__ W,
                              __half* __restrict__ hi, __half* __restrict__ lo,
                              int n)
{
    int i = blockIdx.x * blockDim.x + threadIdx.x;
    if (i < n) {
        float x = W[i];
        __half h = __float2half_rn(x);
        hi[i] = h;
        lo[i] = __float2half_rn(x - __half2float(h));
    }
}

extern "C" void kernel_launch(void* const* d_in, const int* in_sizes, int n_in,
                              void* d_out, int out_size)
{
    (void)in_sizes; (void)n_in; (void)out_size;
    const float* x0 = (const float*)d_in[0];
    // d_in[1] is T (int32, always 11) — baked into the graph.
    const float* W1 = (const float*)d_in[2];
    const float* b1 = (const float*)d_in[3];
    const float* W2 = (const float*)d_in[4];
    const float* b2 = (const float*)d_in[5];
    const float* W3 = (const float*)d_in[6];
    const float* b3 = (const float*)d_in[7];
    float* out = (float*)d_out;

    float *y, *ycmb, *h1, *h2, *kbase;
    __half *w1h, *w1l, *w2h, *w2l, *w3h, *w3l;
    cudaGetSymbolAddress((void**)&y,     g_y);
    cudaGetSymbolAddress((void**)&ycmb,  g_ycmb);
    cudaGetSymbolAddress((void**)&h1,    g_h1);
    cudaGetSymbolAddress((void**)&h2,    g_h2);
    cudaGetSymbolAddress((void**)&kbase, g_k);
    cudaGetSymbolAddress((void**)&w1h,   g_W1hi);
    cudaGetSymbolAddress((void**)&w1l,   g_W1lo);
    cudaGetSymbolAddress((void**)&w2h,   g_W2hi);
    cudaGetSymbolAddress((void**)&w2l,   g_W2lo);
    cudaGetSymbolAddress((void**)&w3h,   g_W3hi);
    cudaGetSymbolAddress((void**)&w3l,   g_W3lo);
    float* k[6];
    for (int j = 0; j < 6; j++) k[j] = kbase + (size_t)j * BB * DD;

    // 3 buffers of (2*AB + 2*WB)
    const int SM12 = 3 * (2 * 64 * 128 + 2 * 64 * 128);   // MT=2: 98304
    const int SM3  = 3 * (2 * 32 * 128 + 2 * 64 * 128);   // MT=1: 73728
    cudaFuncSetAttribute((const void*)&gemm_tc<2, 0>,
                         cudaFuncAttributeMaxDynamicSharedMemorySize, SM12);
    cudaFuncSetAttribute((const void*)&gemm_tc<1, 1>,
                         cudaFuncAttributeMaxDynamicSharedMemorySize, SM3);

    // y = x0[:,0,:]
    cudaMemcpyAsync(y, x0, sizeof(float) * BB * DD, cudaMemcpyDeviceToDevice);

    wsplit_kernel<<<(HH * DD + 255) / 256, 256>>>(W1, w1h, w1l, HH * DD);
    wsplit_kernel<<<(HH * HH + 255) / 256, 256>>>(W2, w2h, w2l, HH * HH);
    wsplit_kernel<<<(DD * HH + 255) / 256, 256>>>(W3, w3h, w3l, DD * HH);

    // Dopri5 tableau
    const double A2[] = {1.0/5.0};
    const double A3[] = {3.0/40.0, 9.0/40.0};
    const double A4[] = {44.0/45.0, -56.0/15.0, 32.0/9.0};
    const double A5[] = {19372.0/6561.0, -25360.0/2187.0, 64448.0/6561.0, -212.0/729.0};
    const double A6[] = {9017.0/3168.0, -355.0/33.0, 46732.0/5247.0, 49.0/176.0, -5103.0/18656.0};
    const double* Arows[5] = {A2, A3, A4, A5, A6};

    const dim3 grd1(HH / 64, BB / 64);   // 8 x 16 = 128 CTAs
    const dim3 grd2(HH / 64, BB / 64);   // 128 CTAs
    const dim3 grd3(DD / 64, BB / 32);   // 4 x 32 = 128 CTAs

    Epi enone = {};

    for (int step = 0; step < N_STEPS; step++) {
        for (int s = 0; s < 6; s++) {
            const float* Ain = (s == 0) ? y : ycmb;
            gemm_tc<2, 0><<<grd1, 256, SM12>>>(Ain, w1h, w1l, b1, h1, DD, HH, enone);
            gemm_tc<2, 0><<<grd2, 256, SM12>>>(h1,  w2h, w2l, b2, h2, HH, HH, enone);

            Epi ep = {};
            ep.yin = y;
            if (s < 5) {
                const double* row = Arows[s];
                ep.nks = s;
                for (int j = 0; j < s; j++) {
                    ep.ks[j]  = k[j];
                    ep.cks[j] = (float)((double)HSTEP * row[j]);
                }
                ep.cself = (float)((double)HSTEP * row[s]);
                ep.aux   = ycmb;
                ep.emit  = nullptr;
                ep.t     = 0;
            } else {
                ep.nks = 4;
                ep.ks[0] = k[0]; ep.cks[0] = (float)((double)HSTEP * (35.0 / 384.0));
                ep.ks[1] = k[2]; ep.cks[1] = (float)((double)HSTEP * (500.0 / 1113.0));
                ep.ks[2] = k[3]; ep.cks[2] = (float)((double)HSTEP * (125.0 / 192.0));
                ep.ks[3] = k[4]; ep.cks[3] = (float)((double)HSTEP * (-2187.0 / 6784.0));
                ep.cself = (float)((double)HSTEP * (11.0 / 84.0));
                ep.aux   = y;
                ep.emit  = ((step & 3) == 3) ? out : nullptr;
                ep.t     = step >> 2;
            }
            gemm_tc<1, 1><<<grd3, 256, SM3>>>(h2, w3h, w3l, b3, k[s], HH, DD, ep);
        }
    }
}